// round 1
// baseline (speedup 1.0000x reference)
#include <cuda_runtime.h>
#include <cuda_bf16.h>

// ---------------------------------------------------------------------------
// GraphCritic: GCNConv -> per-feature median -> tanh MLP -> scalar
//   N=100000 nodes, F=128 features, H=64 hidden, E=1.6M edges
// Pipeline:
//   1) deg[v] = 1 + #in-edges(v); dinv = rsqrt(deg)
//   2) y = D^-1/2 (A+I) D^-1/2 x        (aggregate BEFORE linear: same math)
//   3) h = y @ W^T + b                  (fp32 GEMM via packed fma.rn.f32x2)
//   4) med[f] = k-th smallest of h[:,f], k=(N-1)/2   (4x 8-bit radix select)
//   5) out = w3 @ tanh(w2 @ tanh(w1 @ med + b1) + b2) + b3
// ---------------------------------------------------------------------------

#define NF 128
#define NH 64
#define NMAX 100000

__device__ float g_y[NMAX * NF];      // aggregated features
__device__ float g_h[NMAX * NF];      // post-GEMM features
__device__ float g_dinv[NMAX];
__device__ int   g_deg[NMAX];
__device__ int   g_hist[256 * NF];    // radix histograms [bin*128 + f]
__device__ unsigned g_kprefix[NF];
__device__ int      g_rank[NF];
__device__ float    g_med[NF];

// ---------------- helpers -------------------------------------------------

__device__ __forceinline__ unsigned long long pack2(float a) {
    unsigned long long r;
    asm("mov.b64 %0, {%1, %1};" : "=l"(r) : "f"(a));
    return r;
}
__device__ __forceinline__ unsigned long long pack2(float a, float b) {
    unsigned long long r;
    asm("mov.b64 %0, {%1, %2};" : "=l"(r) : "f"(a), "f"(b));
    return r;
}
__device__ __forceinline__ void unpack2(unsigned long long v, float& lo, float& hi) {
    asm("mov.b64 {%0, %1}, %2;" : "=f"(lo), "=f"(hi) : "l"(v));
}
__device__ __forceinline__ void fma2(unsigned long long& acc, unsigned long long a,
                                     unsigned long long b) {
    asm("fma.rn.f32x2 %0, %1, %2, %0;" : "+l"(acc) : "l"(a), "l"(b));
}
__device__ __forceinline__ void red_add_v4(float* p, float a, float b, float c, float d) {
    asm volatile("red.global.add.v4.f32 [%0], {%1, %2, %3, %4};"
                 :: "l"(p), "f"(a), "f"(b), "f"(c), "f"(d) : "memory");
}
// order-preserving float -> uint key
__device__ __forceinline__ unsigned f2k(float v) {
    unsigned u = __float_as_uint(v);
    return u ^ (((int)u >> 31) | 0x80000000u);
}
__device__ __forceinline__ float k2f(unsigned k) {
    unsigned m = (k & 0x80000000u) ? 0x80000000u : 0xFFFFFFFFu;
    return __uint_as_float(k ^ m);
}

// ---------------- 1) degree / dinv ----------------------------------------

__global__ void k_init(int n, int rank0) {
    int i = blockIdx.x * blockDim.x + threadIdx.x;
    if (i < n) g_deg[i] = 1;                 // self-loop
    if (i < 256 * NF) g_hist[i] = 0;
    if (i < NF) { g_kprefix[i] = 0u; g_rank[i] = rank0; }
}

__global__ void k_count(const int* __restrict__ dst, int e) {
    int i = blockIdx.x * blockDim.x + threadIdx.x;
    if (i < e) atomicAdd(&g_deg[dst[i]], 1);
}

__global__ void k_dinv(int n) {
    int i = blockIdx.x * blockDim.x + threadIdx.x;
    if (i < n) g_dinv[i] = rsqrtf((float)g_deg[i]);
}

// ---------------- 2) aggregation ------------------------------------------

// self-loop term doubles as y's initialization: y[v] = x[v] * dinv[v]^2
__global__ void k_selfinit(const float4* __restrict__ x4, int n4) {
    int i = blockIdx.x * blockDim.x + threadIdx.x;
    if (i >= n4) return;
    int node = i >> 5;
    float s = g_dinv[node]; s *= s;
    float4 v = x4[i];
    v.x *= s; v.y *= s; v.z *= s; v.w *= s;
    ((float4*)g_y)[i] = v;
}

// one warp per edge: gather full 512B x[src] row, vector-atomic into y[dst]
__global__ void k_edges(const float4* __restrict__ x4, const int* __restrict__ src,
                        const int* __restrict__ dst, int e) {
    int eid = (blockIdx.x * blockDim.x + threadIdx.x) >> 5;
    if (eid >= e) return;
    int lane = threadIdx.x & 31;
    int s = __ldg(src + eid);
    int d = __ldg(dst + eid);
    float nrm = __ldg(g_dinv + s) * __ldg(g_dinv + d);
    float4 v = __ldg(x4 + s * 32 + lane);
    red_add_v4(g_y + d * NF + lane * 4, v.x * nrm, v.y * nrm, v.z * nrm, v.w * nrm);
}

// ---------------- 3) GEMM h = y @ W^T + b  (fp32, packed f32x2) -----------

// Tile: 64 rows x 128 cols per CTA, 256 threads.
// Thread (px = tid&7, ry = tid>>3) computes rows {ry, ry+32} x 8 pair-cols
// {px, px+8, ..., px+56} (conflict-free W smem access, broadcast y access).
#define GEMM_SMEM (128 * 64 * 8 + 64 * 132 * 4)   // 65536 + 33792 = 99328 B

__global__ void __launch_bounds__(256, 2)
k_gemm(const float* __restrict__ W, const float* __restrict__ bias, int nrows) {
    extern __shared__ char smraw[];
    unsigned long long* ws2 = (unsigned long long*)smraw;        // [k=128][j2=64]
    float* ys = (float*)(smraw + 128 * 64 * 8);                  // [64][132]
    int tid = threadIdx.x;

    // pack W: ws2[k][j2] = {W[2j2][k], W[2j2+1][k]}  (one-time per CTA, L2-hot)
    for (int idx = tid; idx < 128 * 64; idx += 256) {
        int j2 = idx & 63, k = idx >> 6;
        ws2[k * 64 + j2] = pack2(W[(2 * j2) * 128 + k], W[(2 * j2 + 1) * 128 + k]);
    }
    __syncthreads();

    int nTiles = (nrows + 63) >> 6;
    int px = tid & 7, ry = tid >> 3;

    for (int tile = blockIdx.x; tile < nTiles; tile += gridDim.x) {
        int row0 = tile << 6;
        // stage y tile
        for (int i = tid; i < 64 * 32; i += 256) {
            int r = i >> 5, c = i & 31;
            float4 v = (row0 + r < nrows) ? ((const float4*)g_y)[(row0 + r) * 32 + c]
                                          : make_float4(0.f, 0.f, 0.f, 0.f);
            *(float4*)&ys[r * 132 + c * 4] = v;
        }
        __syncthreads();

        unsigned long long acc0[8] = {0,0,0,0,0,0,0,0};
        unsigned long long acc1[8] = {0,0,0,0,0,0,0,0};
        const float* ya = ys + ry * 132;
        const float* yb = ys + (ry + 32) * 132;
        #pragma unroll 8
        for (int k = 0; k < 128; k++) {
            unsigned long long a0 = pack2(ya[k]);
            unsigned long long a1 = pack2(yb[k]);
            const unsigned long long* wk = ws2 + k * 64 + px;
            #pragma unroll
            for (int j = 0; j < 8; j++) {
                unsigned long long w = wk[8 * j];
                fma2(acc0[j], a0, w);
                fma2(acc1[j], a1, w);
            }
        }
        __syncthreads();   // done reading ys; reuse as output-transpose buffer

        #pragma unroll
        for (int j = 0; j < 8; j++) {
            int col = 2 * (px + 8 * j);
            float lo, hi;
            unpack2(acc0[j], lo, hi);
            ys[ry * 132 + col] = lo; ys[ry * 132 + col + 1] = hi;
            unpack2(acc1[j], lo, hi);
            ys[(ry + 32) * 132 + col] = lo; ys[(ry + 32) * 132 + col + 1] = hi;
        }
        __syncthreads();

        for (int i = tid; i < 64 * 32; i += 256) {
            int r = i >> 5, c = i & 31;
            if (row0 + r < nrows) {
                float4 v = *(float4*)&ys[r * 132 + c * 4];
                float4 b4 = ((const float4*)bias)[c];
                v.x += b4.x; v.y += b4.y; v.z += b4.z; v.w += b4.w;
                ((float4*)g_h)[(row0 + r) * 32 + c] = v;
            }
        }
        __syncthreads();
    }
}

// ---------------- 4) radix-select median (all 128 features at once) -------

#define HIST_SMEM (256 * 129 * 4)   // 129-pitch: conflict-light smem atomics

template <int SHIFT>
__global__ void __launch_bounds__(1024, 1)
k_hist(int nvec) {
    extern __shared__ int sh[];                 // [256][129]
    __shared__ unsigned spref[NF];
    int tid = threadIdx.x;
    for (int i = tid; i < 256 * 129; i += blockDim.x) sh[i] = 0;
    if (tid < NF) spref[tid] = g_kprefix[tid];
    __syncthreads();

    int stride = gridDim.x * blockDim.x;
    for (int i = blockIdx.x * blockDim.x + tid; i < nvec; i += stride) {
        float4 v = ((const float4*)g_h)[i];
        int fb = (i & 31) * 4;
        unsigned k0 = f2k(v.x), k1 = f2k(v.y), k2 = f2k(v.z), k3 = f2k(v.w);
        if constexpr (SHIFT == 24) {
            atomicAdd(&sh[((k0 >> SHIFT) & 255) * 129 + fb + 0], 1);
            atomicAdd(&sh[((k1 >> SHIFT) & 255) * 129 + fb + 1], 1);
            atomicAdd(&sh[((k2 >> SHIFT) & 255) * 129 + fb + 2], 1);
            atomicAdd(&sh[((k3 >> SHIFT) & 255) * 129 + fb + 3], 1);
        } else {
            if ((k0 >> (SHIFT + 8)) == spref[fb + 0])
                atomicAdd(&sh[((k0 >> SHIFT) & 255) * 129 + fb + 0], 1);
            if ((k1 >> (SHIFT + 8)) == spref[fb + 1])
                atomicAdd(&sh[((k1 >> SHIFT) & 255) * 129 + fb + 1], 1);
            if ((k2 >> (SHIFT + 8)) == spref[fb + 2])
                atomicAdd(&sh[((k2 >> SHIFT) & 255) * 129 + fb + 2], 1);
            if ((k3 >> (SHIFT + 8)) == spref[fb + 3])
                atomicAdd(&sh[((k3 >> SHIFT) & 255) * 129 + fb + 3], 1);
        }
    }
    __syncthreads();
    for (int i = tid; i < 256 * NF; i += blockDim.x) {
        int b = i >> 7, f = i & 127;
        int v = sh[b * 129 + f];
        if (v) atomicAdd(&g_hist[i], v);
    }
}

// one warp per feature: find the bin containing the current rank
__global__ void k_select(int shift) {
    int f = (blockIdx.x * blockDim.x + threadIdx.x) >> 5;
    int lane = threadIdx.x & 31;
    if (f >= NF) return;
    int c[8]; int s = 0;
    #pragma unroll
    for (int i = 0; i < 8; i++) { c[i] = g_hist[(lane * 8 + i) * NF + f]; s += c[i]; }
    int pre = s;
    #pragma unroll
    for (int d = 1; d < 32; d <<= 1) {
        int t = __shfl_up_sync(0xffffffff, pre, d);
        if (lane >= d) pre += t;
    }
    int excl = pre - s;
    int r = g_rank[f];
    bool found = (excl <= r) && (r < excl + s);
    if (found) {
        int cum = excl, bin = -1, base = excl;
        #pragma unroll
        for (int i = 0; i < 8; i++) {
            if (bin < 0 && r < cum + c[i]) { bin = lane * 8 + i; base = cum; }
            cum += c[i];
        }
        unsigned np = (g_kprefix[f] << 8) | (unsigned)bin;
        g_kprefix[f] = np;
        g_rank[f] = r - base;
        if (shift == 0) g_med[f] = k2f(np);
    }
    #pragma unroll
    for (int i = 0; i < 8; i++) g_hist[(lane * 8 + i) * NF + f] = 0;  // re-arm
}

// ---------------- 5) MLP ---------------------------------------------------

__global__ void k_mlp(const float* __restrict__ w1, const float* __restrict__ b1,
                      const float* __restrict__ w2, const float* __restrict__ b2,
                      const float* __restrict__ w3, const float* __restrict__ b3,
                      float* __restrict__ out) {
    __shared__ float a1[NH], a2[NH];
    int t = threadIdx.x;
    if (t < NH) {
        float s = b1[t];
        #pragma unroll 4
        for (int f = 0; f < NF; f++) s += g_med[f] * w1[t * NF + f];
        a1[t] = tanhf(s);
    }
    __syncthreads();
    if (t < NH) {
        float s = b2[t];
        #pragma unroll 4
        for (int j = 0; j < NH; j++) s += a1[j] * w2[t * NH + j];
        a2[t] = tanhf(s);
    }
    __syncthreads();
    if (t == 0) {
        float s = b3[0];
        for (int j = 0; j < NH; j++) s += a2[j] * w3[j];
        out[0] = s;
    }
}

// ---------------- launch ---------------------------------------------------

extern "C" void kernel_launch(void* const* d_in, const int* in_sizes, int n_in,
                              void* d_out, int out_size) {
    const float* x  = (const float*)d_in[0];
    const int*   ei = (const int*)d_in[1];
    const float* W  = (const float*)d_in[2];
    const float* cb = (const float*)d_in[3];
    const float* w1 = (const float*)d_in[4];
    const float* b1 = (const float*)d_in[5];
    const float* w2 = (const float*)d_in[6];
    const float* b2 = (const float*)d_in[7];
    const float* w3 = (const float*)d_in[8];
    const float* b3 = (const float*)d_in[9];

    int N = in_sizes[0] / NF;
    int E = in_sizes[1] / 2;
    const int* src = ei;
    const int* dst = ei + E;

    static bool attr_done = false;
    if (!attr_done) {
        cudaFuncSetAttribute(k_gemm, cudaFuncAttributeMaxDynamicSharedMemorySize, GEMM_SMEM);
        cudaFuncSetAttribute(k_hist<24>, cudaFuncAttributeMaxDynamicSharedMemorySize, HIST_SMEM);
        cudaFuncSetAttribute(k_hist<16>, cudaFuncAttributeMaxDynamicSharedMemorySize, HIST_SMEM);
        cudaFuncSetAttribute(k_hist<8>,  cudaFuncAttributeMaxDynamicSharedMemorySize, HIST_SMEM);
        cudaFuncSetAttribute(k_hist<0>,  cudaFuncAttributeMaxDynamicSharedMemorySize, HIST_SMEM);
        attr_done = true;
    }

    int nvec = N * (NF / 4);  // number of float4 in [N,F]

    k_init<<<(N + 255) / 256, 256>>>(N, (N - 1) / 2);
    k_count<<<(E + 255) / 256, 256>>>(dst, E);
    k_dinv<<<(N + 255) / 256, 256>>>(N);
    k_selfinit<<<(nvec + 255) / 256, 256>>>((const float4*)x, nvec);
    k_edges<<<(E + 7) / 8, 256>>>((const float4*)x, src, dst, E);
    k_gemm<<<296, 256, GEMM_SMEM>>>(W, cb, N);

    k_hist<24><<<148, 1024, HIST_SMEM>>>(nvec);
    k_select<<<4, 1024>>>(24);
    k_hist<16><<<148, 1024, HIST_SMEM>>>(nvec);
    k_select<<<4, 1024>>>(16);
    k_hist<8><<<148, 1024, HIST_SMEM>>>(nvec);
    k_select<<<4, 1024>>>(8);
    k_hist<0><<<148, 1024, HIST_SMEM>>>(nvec);
    k_select<<<4, 1024>>>(0);

    k_mlp<<<1, 128>>>(w1, b1, w2, b2, w3, b3, (float*)d_out);
}